// round 6
// baseline (speedup 1.0000x reference)
#include <cuda_runtime.h>

#define NN 32
#define CC 1024
#define NT 1024

// dynamic smem layout
#define OFF_ROWS 0                      // float [32][1024]  = 131072
#define OFF_D    131072                 // float [32][32]    = 4096
#define OFF_VAL  135168                 // u32   [32]        = 128
#define OFF_IDX  135296                 // u32   [32]        = 128
#define OFF_SQ   135424                 // float [32]        = 128
#define OFF_L    135552                 // int   [32]        = 128
#define SMEM_TOTAL 135680

__device__ __forceinline__ float warp_sum(float v) {
    #pragma unroll
    for (int o = 16; o; o >>= 1) v += __shfl_down_sync(0xffffffffu, v, o);
    return v;
}

// four interleaved warp reductions (independent chains pipeline SHFL latency)
__device__ __forceinline__ void warp_sum4(float& a, float& b, float& c, float& d) {
    #pragma unroll
    for (int o = 16; o; o >>= 1) {
        a += __shfl_down_sync(0xffffffffu, a, o);
        b += __shfl_down_sync(0xffffffffu, b, o);
        c += __shfl_down_sync(0xffffffffu, c, o);
        d += __shfl_down_sync(0xffffffffu, d, o);
    }
}

__global__ __launch_bounds__(NT, 1)
void merge_tree_kernel(const float* __restrict__ x,
                       const float* __restrict__ cw,
                       const float* __restrict__ cb,
                       float* __restrict__ out)
{
    extern __shared__ unsigned char sm_raw[];
    float*    rows = (float*)(sm_raw + OFF_ROWS);
    float*    D    = (float*)(sm_raw + OFF_D);
    unsigned* vals = (unsigned*)(sm_raw + OFF_VAL);
    unsigned* idxs = (unsigned*)(sm_raw + OFF_IDX);
    float*    sq   = (float*)(sm_raw + OFF_SQ);
    int*      L    = (int*)(sm_raw + OFF_L);

    const int tid  = threadIdx.x;
    const int lane = tid & 31;
    const int warp = tid >> 5;
    const int b    = blockIdx.x;

    // ---- load batch rows (coalesced float4) ----
    {
        const float4* xb4 = (const float4*)(x + (size_t)b * (NN * CC));
        float4* r4 = (float4*)rows;
        #pragma unroll
        for (int i = tid; i < NN * CC / 4; i += NT) r4[i] = xb4[i];
    }
    const float w00 = cw[0], w01 = cw[1], w02 = cw[2];
    const float w10 = cw[3], w11 = cw[4], w12 = cw[5];
    const float bv  = cb[0];
    if (tid < NN) L[tid] = tid;
    __syncthreads();

    // ---- cache own row in registers; norms (fp32, 4-chain) ----
    float4 rv[8];
    {
        const float4* r4w = (const float4*)(rows + warp * CC);
        #pragma unroll
        for (int k = 0; k < 8; k++) rv[k] = r4w[lane + 32 * k];
        float a0 = 0, a1 = 0, a2 = 0, a3 = 0;
        #pragma unroll
        for (int k = 0; k < 8; k++) {
            a0 = fmaf(rv[k].x, rv[k].x, a0);
            a1 = fmaf(rv[k].y, rv[k].y, a1);
            a2 = fmaf(rv[k].z, rv[k].z, a2);
            a3 = fmaf(rv[k].w, rv[k].w, a3);
        }
        float s = warp_sum((a0 + a1) + (a2 + a3));
        if (!lane) sq[warp] = s;
    }
    __syncthreads();

    // ---- initial gram, balanced rotation: warp w handles pair (w, (w+k)&31)
    //      for k=1..15, plus k=16 for w<16. Each unordered pair exactly once.
    //      FMA multiply commutes, so dot value == canonical (i<j) order. ----
    {
        const float sqi = sq[warp];
        #pragma unroll 1
        for (int k = 1; k <= 16; k++) {
            if (k == 16 && warp >= 16) break;
            const int j = (warp + k) & 31;
            const float4* rj4 = (const float4*)(rows + j * CC);
            float a0 = 0, a1 = 0, a2 = 0, a3 = 0;
            #pragma unroll
            for (int q = 0; q < 8; q++) {
                float4 v = rj4[lane + 32 * q];
                a0 = fmaf(rv[q].x, v.x, a0);
                a1 = fmaf(rv[q].y, v.y, a1);
                a2 = fmaf(rv[q].z, v.z, a2);
                a3 = fmaf(rv[q].w, v.w, a3);
            }
            float dot = warp_sum((a0 + a1) + (a2 + a3));
            if (!lane) {
                float d2 = sqi + sq[j] - 2.0f * dot;
                float d  = sqrtf(fmaxf(d2, 0.f));
                D[warp * NN + j] = d;
                D[j * NN + warp] = d;
            }
        }
    }
    __syncthreads();

    // ==== 31 merge steps, 4 barriers each ====
    int n = NN;
    const int pi = warp;              // argmin pair grid: i = warp, j = lane
    const int pj = lane;
    for (int step = 0; step < NN - 1; step++, n--) {
        // -- P1: argmin via REDUX + ballot (value, lexicographic tie-break) --
        unsigned dv = 0xffffffffu;    // +inf sentinel (bit order of nonneg f32)
        if (pi < pj && pj < n) dv = __float_as_uint(D[L[pi] * NN + L[pj]]);
        unsigned wmin = __reduce_min_sync(0xffffffffu, dv);
        unsigned bal  = __ballot_sync(0xffffffffu, dv == wmin);
        if (!lane) {
            int jw = __ffs(bal) - 1;            // lowest lane = smallest j
            vals[warp] = wmin;
            idxs[warp] = (unsigned)((pi << 5) | jw);
        }
        __syncthreads();                         // bar A

        unsigned v  = vals[lane];
        unsigned gm = __reduce_min_sync(0xffffffffu, v);
        unsigned b2 = __ballot_sync(0xffffffffu, v == gm);
        const unsigned k32 = idxs[__ffs(b2) - 1]; // lowest warp = smallest i

        const int a   = (k32 >> 5) & 31;
        const int bbj = k32 & 31;
        const int ra  = L[a];
        const int rb  = L[bbj];
        const int dst = L[(a == 1) ? 0 : a];     // freed slot hosts merged row

        // -- P2: conv1d(2ch->1ch,k=3,SAME)+bias+relu; new L from old L --
        const float* Xa = rows + ra * CC;
        const float* Xb = rows + rb * CC;
        const int h = tid;
        float a1v = Xa[h], b1v = Xb[h];
        float a0v = (h > 0)      ? Xa[h - 1] : 0.f;
        float a2v = (h < CC - 1) ? Xa[h + 1] : 0.f;
        float b0v = (h > 0)      ? Xb[h - 1] : 0.f;
        float b2v = (h < CC - 1) ? Xb[h + 1] : 0.f;
        float m = fmaf(w00, a0v, fmaf(w01, a1v, fmaf(w02, a2v,
                  fmaf(w10, b0v, fmaf(w11, b1v, fmaf(w12, b2v, bv))))));
        m = fmaxf(m, 0.f);

        int newv = 0;
        if (tid < n - 1) {
            if (tid == 0) newv = dst;
            else {
                int pp  = tid + 1;
                int src = (pp == a) ? 0 : ((pp == bbj) ? 1 : pp);
                newv = L[src];
            }
        }
        __syncthreads();                         // bar B: rows/L reads done

        // -- P3: commit merged row + new logical map --
        rows[dst * CC + h] = m;
        if (tid < n - 1) L[tid] = newv;
        __syncthreads();                         // bar C

        // -- P4: THREE survivors per warp; m row loaded once per warp.
        //        msq reduced from the same m values; per-survivor accumulation
        //        chains identical to before (bit-identical dots). --
        const int cnt = n - 2;                   // survivors = new logical 1..n-2
        const int nw  = (cnt + 2) / 3;
        if (warp < nw) {
            const int j0 = 3 * warp;
            const int j1 = j0 + 1;
            const int j2 = j0 + 2;
            const int c1ok = (j1 < cnt);
            const int c2ok = (j2 < cnt);
            const int s0 = L[1 + j0];
            const int s1 = L[1 + (c1ok ? j1 : j0)];
            const int s2 = L[1 + (c2ok ? j2 : j0)];
            const float4* rm  = (const float4*)(rows + dst * CC);
            const float4* rs0 = (const float4*)(rows + s0 * CC);
            const float4* rs1 = (const float4*)(rows + s1 * CC);
            const float4* rs2 = (const float4*)(rows + s2 * CC);
            float A0=0,A1=0,A2=0,A3=0;
            float B0=0,B1=0,B2=0,B3=0;
            float C0=0,C1=0,C2=0,C3=0;
            float M0=0,M1=0,M2=0,M3=0;
            #pragma unroll
            for (int k = 0; k < 8; k++) {
                float4 u  = rm [lane + 32 * k];
                float4 v0 = rs0[lane + 32 * k];
                float4 v1 = rs1[lane + 32 * k];
                float4 v2 = rs2[lane + 32 * k];
                A0 = fmaf(u.x, v0.x, A0);
                A1 = fmaf(u.y, v0.y, A1);
                A2 = fmaf(u.z, v0.z, A2);
                A3 = fmaf(u.w, v0.w, A3);
                B0 = fmaf(u.x, v1.x, B0);
                B1 = fmaf(u.y, v1.y, B1);
                B2 = fmaf(u.z, v1.z, B2);
                B3 = fmaf(u.w, v1.w, B3);
                C0 = fmaf(u.x, v2.x, C0);
                C1 = fmaf(u.y, v2.y, C1);
                C2 = fmaf(u.z, v2.z, C2);
                C3 = fmaf(u.w, v2.w, C3);
                M0 = fmaf(u.x, u.x, M0);
                M1 = fmaf(u.y, u.y, M1);
                M2 = fmaf(u.z, u.z, M2);
                M3 = fmaf(u.w, u.w, M3);
            }
            float d0  = (A0 + A1) + (A2 + A3);
            float d1  = (B0 + B1) + (B2 + B3);
            float d2s = (C0 + C1) + (C2 + C3);
            float msq = (M0 + M1) + (M2 + M3);
            warp_sum4(d0, d1, d2s, msq);
            if (!lane) {
                float e0 = sqrtf(fmaxf(msq + sq[s0] - 2.0f * d0, 0.f));
                D[dst * NN + s0] = e0;
                D[s0 * NN + dst] = e0;
                if (c1ok) {
                    float e1 = sqrtf(fmaxf(msq + sq[s1] - 2.0f * d1, 0.f));
                    D[dst * NN + s1] = e1;
                    D[s1 * NN + dst] = e1;
                }
                if (c2ok) {
                    float e2 = sqrtf(fmaxf(msq + sq[s2] - 2.0f * d2s, 0.f));
                    D[dst * NN + s2] = e2;
                    D[s2 * NN + dst] = e2;
                }
                if (warp == 0) sq[dst] = msq;    // persist merged norm
            }
        }
        __syncthreads();                         // bar D: D, sq ready for next argmin
    }

    // final merged row lives at slot L[0]
    out[(size_t)b * CC + tid] = rows[L[0] * CC + tid];
}

extern "C" void kernel_launch(void* const* d_in, const int* in_sizes, int n_in,
                              void* d_out, int out_size)
{
    const float* x  = (const float*)d_in[0];
    const float* cw = (const float*)d_in[1];
    const float* cb = (const float*)d_in[2];
    float* out = (float*)d_out;

    int B = in_sizes[0] / (NN * CC);

    cudaFuncSetAttribute(merge_tree_kernel,
                         cudaFuncAttributeMaxDynamicSharedMemorySize,
                         SMEM_TOTAL);
    merge_tree_kernel<<<B, NT, SMEM_TOTAL>>>(x, cw, cb, out);
}

// round 7
// speedup vs baseline: 1.0159x; 1.0159x over previous
#include <cuda_runtime.h>

#define NN 32
#define CC 1024
#define NT 1024
#define FULLM 0xffffffffu

// dynamic smem layout
#define OFF_ROWS 0                      // float [32][1024]  = 131072
#define OFF_D    131072                 // float [32][32]    = 4096
#define OFF_VAL  135168                 // u32   [32]        = 128
#define OFF_IDX  135296                 // u32   [32]        = 128
#define OFF_SQ   135424                 // float [32]        = 128
#define OFF_L    135552                 // int   [32]        = 128
#define SMEM_TOTAL 135680

typedef unsigned long long u64;

__device__ __forceinline__ float warp_sum(float v) {
    #pragma unroll
    for (int o = 16; o; o >>= 1) v += __shfl_down_sync(FULLM, v, o);
    return v;
}

__device__ __forceinline__ void warp_sum4(float& a, float& b, float& c, float& d) {
    #pragma unroll
    for (int o = 16; o; o >>= 1) {
        a += __shfl_down_sync(FULLM, a, o);
        b += __shfl_down_sync(FULLM, b, o);
        c += __shfl_down_sync(FULLM, c, o);
        d += __shfl_down_sync(FULLM, d, o);
    }
}

__global__ __launch_bounds__(NT, 1)
void merge_tree_kernel(const float* __restrict__ x,
                       const float* __restrict__ cw,
                       const float* __restrict__ cb,
                       float* __restrict__ out)
{
    extern __shared__ unsigned char sm_raw[];
    float*    rows = (float*)(sm_raw + OFF_ROWS);
    float*    D    = (float*)(sm_raw + OFF_D);
    unsigned* vals = (unsigned*)(sm_raw + OFF_VAL);
    unsigned* idxs = (unsigned*)(sm_raw + OFF_IDX);
    float*    sq   = (float*)(sm_raw + OFF_SQ);
    int*      L    = (int*)(sm_raw + OFF_L);

    const int tid  = threadIdx.x;
    const int lane = tid & 31;
    const int warp = tid >> 5;
    const int b    = blockIdx.x;

    // ---- load batch rows (coalesced float4) ----
    {
        const float4* xb4 = (const float4*)(x + (size_t)b * (NN * CC));
        float4* r4 = (float4*)rows;
        #pragma unroll
        for (int i = tid; i < NN * CC / 4; i += NT) r4[i] = xb4[i];
    }
    const float w00 = cw[0], w01 = cw[1], w02 = cw[2];
    const float w10 = cw[3], w11 = cw[4], w12 = cw[5];
    const float bv  = cb[0];
    if (tid < NN) L[tid] = tid;
    __syncthreads();

    // ---- cache own row in registers; norms (fp32, 4-chain) ----
    float4 rv[8];
    {
        const float4* r4w = (const float4*)(rows + warp * CC);
        #pragma unroll
        for (int k = 0; k < 8; k++) rv[k] = r4w[lane + 32 * k];
        float a0 = 0, a1 = 0, a2 = 0, a3 = 0;
        #pragma unroll
        for (int k = 0; k < 8; k++) {
            a0 = fmaf(rv[k].x, rv[k].x, a0);
            a1 = fmaf(rv[k].y, rv[k].y, a1);
            a2 = fmaf(rv[k].z, rv[k].z, a2);
            a3 = fmaf(rv[k].w, rv[k].w, a3);
        }
        float s = warp_sum((a0 + a1) + (a2 + a3));
        if (!lane) sq[warp] = s;
    }
    __syncthreads();

    // ---- initial gram, balanced rotation: warp w does pair (w,(w+k)&31),
    //      k=1..15, plus k=16 for w<16 (each unordered pair once; FMA
    //      commutes so value == canonical order). ----
    {
        const float sqi = sq[warp];
        #pragma unroll 1
        for (int k = 1; k <= 16; k++) {
            if (k == 16 && warp >= 16) break;
            const int j = (warp + k) & 31;
            const float4* rj4 = (const float4*)(rows + j * CC);
            float a0 = 0, a1 = 0, a2 = 0, a3 = 0;
            #pragma unroll
            for (int q = 0; q < 8; q++) {
                float4 v = rj4[lane + 32 * q];
                a0 = fmaf(rv[q].x, v.x, a0);
                a1 = fmaf(rv[q].y, v.y, a1);
                a2 = fmaf(rv[q].z, v.z, a2);
                a3 = fmaf(rv[q].w, v.w, a3);
            }
            float dot = warp_sum((a0 + a1) + (a2 + a3));
            if (!lane) {
                float d2 = sqi + sq[j] - 2.0f * dot;
                float d  = sqrtf(fmaxf(d2, 0.f));
                D[warp * NN + j] = d;
                D[j * NN + warp] = d;
            }
        }
    }
    __syncthreads();

    // ---- pre-loop argmin partials: warp i scans pairs (i, j>i) ----
    {
        unsigned kv = FULLM, ki = 0x3ffu;
        if (lane > warp) {
            kv = __float_as_uint(D[warp * NN + lane]);
            ki = (unsigned)((warp << 5) | lane);
        }
        unsigned wv = __reduce_min_sync(FULLM, kv);
        unsigned mm = __ballot_sync(FULLM, kv == wv);
        unsigned ci = ((mm >> lane) & 1) ? ki : FULLM;
        unsigned wi = __reduce_min_sync(FULLM, ci);
        if (!lane) { vals[warp] = wv; idxs[warp] = wi; }
    }
    __syncthreads();

    // ==== 31 merge steps, 3 barriers each ====
    int n = NN;
    for (int step = 0; step < NN - 1; step++, n--) {
        // -- combine 32 partials: global (value, lexicographic idx) min --
        unsigned v  = vals[lane];
        unsigned gm = __reduce_min_sync(FULLM, v);
        unsigned mk = __ballot_sync(FULLM, v == gm);
        unsigned cd = ((mk >> lane) & 1) ? idxs[lane] : FULLM;
        unsigned gi = __reduce_min_sync(FULLM, cd);

        const int a   = (gi >> 5) & 31;
        const int bbj = gi & 31;
        const int ra  = L[a];
        const int rb  = L[bbj];
        const int dst = L[(a == 1) ? 0 : a];     // freed slot hosts merged row

        // -- conv1d(2ch->1ch,k=3,SAME)+bias+relu; new L from old L --
        const float* Xa = rows + ra * CC;
        const float* Xb = rows + rb * CC;
        const int h = tid;
        float a1v = Xa[h], b1v = Xb[h];
        float a0v = (h > 0)      ? Xa[h - 1] : 0.f;
        float a2v = (h < CC - 1) ? Xa[h + 1] : 0.f;
        float b0v = (h > 0)      ? Xb[h - 1] : 0.f;
        float b2v = (h < CC - 1) ? Xb[h + 1] : 0.f;
        float m = fmaf(w00, a0v, fmaf(w01, a1v, fmaf(w02, a2v,
                  fmaf(w10, b0v, fmaf(w11, b1v, fmaf(w12, b2v, bv))))));
        m = fmaxf(m, 0.f);

        int newv = 0;
        if (tid < n - 1) {
            if (tid == 0) newv = dst;
            else {
                int pp  = tid + 1;
                int src = (pp == a) ? 0 : ((pp == bbj) ? 1 : pp);
                newv = L[src];
            }
        }
        __syncthreads();                         // bar B: rows/L reads done

        rows[dst * CC + h] = m;
        if (tid < n - 1) L[tid] = newv;          // L now = NEXT config map
        __syncthreads();                         // bar C

        // -- P4: dot warps update merged-row distances AND fold them into
        //    argmin partials; other warps scan survivor-survivor pairs of
        //    the NEXT config (D entries disjoint from dot writes). --
        const int cnt = n - 2;                   // survivors: next logical 1..cnt
        const int nw  = (cnt + 2) / 3;
        if (warp < nw) {                         // implies cnt > 0
            const int j0 = 3 * warp;
            const int j1 = j0 + 1;
            const int j2 = j0 + 2;
            const int c1ok = (j1 < cnt);
            const int c2ok = (j2 < cnt);
            const int s0 = L[1 + j0];
            const int s1 = L[1 + (c1ok ? j1 : j0)];
            const int s2 = L[1 + (c2ok ? j2 : j0)];
            const float4* rm  = (const float4*)(rows + dst * CC);
            const float4* rs0 = (const float4*)(rows + s0 * CC);
            const float4* rs1 = (const float4*)(rows + s1 * CC);
            const float4* rs2 = (const float4*)(rows + s2 * CC);
            float A0=0,A1=0,A2=0,A3=0;
            float B0=0,B1=0,B2=0,B3=0;
            float C0=0,C1=0,C2=0,C3=0;
            float M0=0,M1=0,M2=0,M3=0;
            #pragma unroll
            for (int k = 0; k < 8; k++) {
                float4 u  = rm [lane + 32 * k];
                float4 v0 = rs0[lane + 32 * k];
                float4 v1 = rs1[lane + 32 * k];
                float4 v2 = rs2[lane + 32 * k];
                A0 = fmaf(u.x, v0.x, A0);
                A1 = fmaf(u.y, v0.y, A1);
                A2 = fmaf(u.z, v0.z, A2);
                A3 = fmaf(u.w, v0.w, A3);
                B0 = fmaf(u.x, v1.x, B0);
                B1 = fmaf(u.y, v1.y, B1);
                B2 = fmaf(u.z, v1.z, B2);
                B3 = fmaf(u.w, v1.w, B3);
                C0 = fmaf(u.x, v2.x, C0);
                C1 = fmaf(u.y, v2.y, C1);
                C2 = fmaf(u.z, v2.z, C2);
                C3 = fmaf(u.w, v2.w, C3);
                M0 = fmaf(u.x, u.x, M0);
                M1 = fmaf(u.y, u.y, M1);
                M2 = fmaf(u.z, u.z, M2);
                M3 = fmaf(u.w, u.w, M3);
            }
            float d0  = (A0 + A1) + (A2 + A3);
            float d1  = (B0 + B1) + (B2 + B3);
            float d2s = (C0 + C1) + (C2 + C3);
            float msq = (M0 + M1) + (M2 + M3);
            warp_sum4(d0, d1, d2s, msq);
            if (!lane) {
                float e0 = sqrtf(fmaxf(msq + sq[s0] - 2.0f * d0, 0.f));
                D[dst * NN + s0] = e0;
                D[s0 * NN + dst] = e0;
                u64 kk = ((u64)__float_as_uint(e0) << 32) | (unsigned)(1 + j0);
                if (c1ok) {
                    float e1 = sqrtf(fmaxf(msq + sq[s1] - 2.0f * d1, 0.f));
                    D[dst * NN + s1] = e1;
                    D[s1 * NN + dst] = e1;
                    u64 k1 = ((u64)__float_as_uint(e1) << 32) | (unsigned)(1 + j1);
                    kk = min(kk, k1);
                }
                if (c2ok) {
                    float e2 = sqrtf(fmaxf(msq + sq[s2] - 2.0f * d2s, 0.f));
                    D[dst * NN + s2] = e2;
                    D[s2 * NN + dst] = e2;
                    u64 k2 = ((u64)__float_as_uint(e2) << 32) | (unsigned)(1 + j2);
                    kk = min(kk, k2);
                }
                if (warp == 0) sq[dst] = msq;    // persist merged norm
                vals[warp] = (unsigned)(kk >> 32);
                idxs[warp] = (unsigned)(kk & 0x3ffu);
            }
        } else {
            // survivor-pair argmin partials for next config: pairs (i,j),
            // 1 <= i < j <= cnt, i strided over scan warps
            u64 kk = 0xffffffffffffffffull;
            const int S = 32 - nw;
            for (int i = 1 + (warp - nw); i <= cnt - 1; i += S) {
                if (lane > i && lane <= cnt) {
                    float d = D[L[i] * NN + L[lane]];
                    u64 kc = ((u64)__float_as_uint(d) << 32)
                           | (unsigned)((i << 5) | lane);
                    kk = min(kk, kc);
                }
            }
            unsigned kv = (unsigned)(kk >> 32);
            unsigned wv = __reduce_min_sync(FULLM, kv);
            unsigned mm = __ballot_sync(FULLM, kv == wv);
            unsigned ci = ((mm >> lane) & 1) ? (unsigned)(kk & FULLM) : FULLM;
            unsigned wi = __reduce_min_sync(FULLM, ci);
            if (!lane) { vals[warp] = wv; idxs[warp] = wi & 0x3ffu; }
        }
        __syncthreads();                         // bar_end: D, sq, partials ready
    }

    // final merged row lives at slot L[0]
    out[(size_t)b * CC + tid] = rows[L[0] * CC + tid];
}

extern "C" void kernel_launch(void* const* d_in, const int* in_sizes, int n_in,
                              void* d_out, int out_size)
{
    const float* x  = (const float*)d_in[0];
    const float* cw = (const float*)d_in[1];
    const float* cb = (const float*)d_in[2];
    float* out = (float*)d_out;

    int B = in_sizes[0] / (NN * CC);

    cudaFuncSetAttribute(merge_tree_kernel,
                         cudaFuncAttributeMaxDynamicSharedMemorySize,
                         SMEM_TOTAL);
    merge_tree_kernel<<<B, NT, SMEM_TOTAL>>>(x, cw, cb, out);
}